// round 3
// baseline (speedup 1.0000x reference)
#include <cuda_runtime.h>
#include <cuda_bf16.h>
#include <math.h>

// ---------------------------------------------------------------------------
// Problem constants
// B=4, T=2048, P=16, J=256, H=4, D=16, MEM=64, K_OUT=192
// N = B*P = 64 sequences; tokens M_TOK = N*T = 131072
// x row-major: x[m][j], m = n*T + t (pure reinterpretation of joint_repr flat)
// Fused projection outputs per token (200):
//   [0:64)   q_pre   [64:128) k_pre   [128:192) v   [192:196) beta_pre  [196:200) alpha_pre
// ---------------------------------------------------------------------------

#define M_TOK   131072
#define JDIM    256
#define NOUT    200
#define NSEQ    64
#define TLEN    2048
#define HEADS   4
#define DHEAD   16
#define KOUT    192

// -------- scratch (device globals; no allocation allowed) --------
__device__ float g_Bpack [(size_t)JDIM * NOUT];     // [k][o] k-major, 200 cols
__device__ float g_Bpack2[(size_t)64 * KOUT];       // [k][o] for out_w^T
__device__ float g_pre   [(size_t)M_TOK * NOUT];    // projection pre-activations
__device__ float g_q     [(size_t)M_TOK * 64];
__device__ float g_k     [(size_t)M_TOK * 64];
__device__ float g_v     [(size_t)M_TOK * 64];
__device__ float g_beta  [(size_t)M_TOK * HEADS];
__device__ float g_alpha [(size_t)M_TOK * HEADS];
__device__ float g_o     [(size_t)M_TOK * 64];

// ---------------------------------------------------------------------------
// Kernel 0: pack weights into k-major matrices for the GEMMs
// ---------------------------------------------------------------------------
__global__ void pack_kernel(const float* __restrict__ Wq,
                            const float* __restrict__ Wk,
                            const float* __restrict__ Wv,
                            const float* __restrict__ Wbw,
                            const float* __restrict__ Waw,
                            const float* __restrict__ out_w)
{
    int idx = blockIdx.x * blockDim.x + threadIdx.x;
    if (idx < JDIM * NOUT) {
        int k = idx / NOUT;
        int o = idx - k * NOUT;
        float val;
        if      (o < 64)  val = Wq [(size_t)o        * JDIM + k];
        else if (o < 128) val = Wk [(size_t)(o-64)   * JDIM + k];
        else if (o < 192) val = Wv [(size_t)(o-128)  * JDIM + k];
        else if (o < 196) val = Wbw[(size_t)(o-192)  * JDIM + k];
        else              val = Waw[(size_t)(o-196)  * JDIM + k];
        g_Bpack[idx] = val;
    }
    int idx2 = idx - JDIM * NOUT;
    if (idx2 >= 0 && idx2 < 64 * KOUT) {
        int k = idx2 / KOUT;
        int o = idx2 - k * KOUT;
        g_Bpack2[idx2] = out_w[(size_t)o * 64 + k];
    }
}

// ---------------------------------------------------------------------------
// Kernel A: SGEMM  g_pre[131072,200] = x[131072,256] @ g_Bpack[256,200]
// BM=128, BN=64, BK=16, 256 threads, thread tile 8x4
// ---------------------------------------------------------------------------
#define A_BM 128
#define A_BN 64
#define A_BK 16

__global__ __launch_bounds__(256) void gemmA_kernel(const float* __restrict__ A)
{
    __shared__ __align__(16) float As[A_BK][A_BM];
    __shared__ __align__(16) float Bs[A_BK][A_BN];

    const int tid = threadIdx.x;
    const int tx = tid & 15;    // col group (4 cols each)
    const int ty = tid >> 4;    // row group (8 rows each)
    const int m0 = blockIdx.y * A_BM;
    const int n0 = blockIdx.x * A_BN;

    float acc[8][4];
#pragma unroll
    for (int i = 0; i < 8; i++)
#pragma unroll
        for (int j = 0; j < 4; j++) acc[i][j] = 0.f;

    for (int k0 = 0; k0 < JDIM; k0 += A_BK) {
        // load A tile: 128 rows x 16 k  (512 float4, 2 per thread)
#pragma unroll
        for (int i = 0; i < 2; i++) {
            int e   = i * 256 + tid;      // float4 index
            int row = e >> 2;             // 4 float4 per row
            int kq  = (e & 3) * 4;
            float4 av = *(const float4*)(A + (size_t)(m0 + row) * JDIM + k0 + kq);
            As[kq+0][row] = av.x; As[kq+1][row] = av.y;
            As[kq+2][row] = av.z; As[kq+3][row] = av.w;
        }
        // load B tile: 16 k x 64 cols (scalar, guarded: NOUT=200)
#pragma unroll
        for (int i = 0; i < 4; i++) {
            int e   = i * 256 + tid;
            int kk  = e >> 6;
            int col = e & 63;
            int gc  = n0 + col;
            Bs[kk][col] = (gc < NOUT) ? g_Bpack[(size_t)(k0 + kk) * NOUT + gc] : 0.f;
        }
        __syncthreads();

#pragma unroll
        for (int kk = 0; kk < A_BK; kk++) {
            float4 a0 = *(const float4*)&As[kk][ty * 8];
            float4 a1 = *(const float4*)&As[kk][ty * 8 + 4];
            float4 b0 = *(const float4*)&Bs[kk][tx * 4];
            float ar[8] = {a0.x,a0.y,a0.z,a0.w,a1.x,a1.y,a1.z,a1.w};
            float br[4] = {b0.x,b0.y,b0.z,b0.w};
#pragma unroll
            for (int i = 0; i < 8; i++)
#pragma unroll
                for (int j = 0; j < 4; j++)
                    acc[i][j] = fmaf(ar[i], br[j], acc[i][j]);
        }
        __syncthreads();
    }

#pragma unroll
    for (int i = 0; i < 8; i++) {
        int row = m0 + ty * 8 + i;
#pragma unroll
        for (int j = 0; j < 4; j++) {
            int col = n0 + tx * 4 + j;
            if (col < NOUT) g_pre[(size_t)row * NOUT + col] = acc[i][j];
        }
    }
}

// ---------------------------------------------------------------------------
// Kernel B: epilogue — LN(q), LN + L2 norm(k), v passthrough, double-sigmoid
// beta/alpha with curvature/entropy modulation. One warp per token.
// ---------------------------------------------------------------------------
__device__ __forceinline__ float red16(float x)
{
    x += __shfl_xor_sync(0xffffffffu, x, 8);
    x += __shfl_xor_sync(0xffffffffu, x, 4);
    x += __shfl_xor_sync(0xffffffffu, x, 2);
    x += __shfl_xor_sync(0xffffffffu, x, 1);
    return x;
}
__device__ __forceinline__ float sigm(float x) { return 1.f / (1.f + expf(-x)); }

__global__ __launch_bounds__(256) void epilogue_kernel(
    const float* __restrict__ curv, const float* __restrict__ ent,
    const float* __restrict__ Wbb,  const float* __restrict__ Wab,
    const float* __restrict__ cw,   const float* __restrict__ ew,
    const float* __restrict__ lqw,  const float* __restrict__ lqb,
    const float* __restrict__ lkw,  const float* __restrict__ lkb)
{
    const int tid  = threadIdx.x;
    const int lane = tid & 31;
    const int w    = tid >> 5;
    const size_t m = (size_t)blockIdx.x * 8 + w;
    const float* pre = g_pre + m * NOUT;
    const int di = lane & 15;

    const float wq = lqw[di], bq = lqb[di];
    const float wk = lkw[di], bk = lkb[di];
    const float inv16 = 1.f / 16.f;

    // ---- q: LayerNorm over each head of 16 ----
    float q0 = pre[lane], q1 = pre[32 + lane];
    float mu0 = red16(q0) * inv16, mu1 = red16(q1) * inv16;
    float d0 = q0 - mu0, d1 = q1 - mu1;
    float va0 = red16(d0 * d0) * inv16, va1 = red16(d1 * d1) * inv16;
    float qn0 = d0 / sqrtf(va0 + 1e-5f) * wq + bq;
    float qn1 = d1 / sqrtf(va1 + 1e-5f) * wq + bq;
    g_q[m * 64 + lane]      = qn0;
    g_q[m * 64 + 32 + lane] = qn1;

    // ---- k: LayerNorm then L2 normalize per head ----
    float k0 = pre[64 + lane], k1 = pre[96 + lane];
    float km0 = red16(k0) * inv16, km1 = red16(k1) * inv16;
    float kd0 = k0 - km0, kd1 = k1 - km1;
    float kv0 = red16(kd0 * kd0) * inv16, kv1 = red16(kd1 * kd1) * inv16;
    float kn0 = kd0 / sqrtf(kv0 + 1e-5f) * wk + bk;
    float kn1 = kd1 / sqrtf(kv1 + 1e-5f) * wk + bk;
    float nn0 = red16(kn0 * kn0);
    float nn1 = red16(kn1 * kn1);
    kn0 = kn0 / fmaxf(sqrtf(nn0), 1e-12f);
    kn1 = kn1 / fmaxf(sqrtf(nn1), 1e-12f);
    g_k[m * 64 + lane]      = kn0;
    g_k[m * 64 + 32 + lane] = kn1;

    // ---- v passthrough ----
    g_v[m * 64 + lane]      = pre[128 + lane];
    g_v[m * 64 + 32 + lane] = pre[160 + lane];

    // ---- beta / alpha (double sigmoid with modulation) ----
    if (lane < HEADS) {
        int nidx = (int)(m >> 11);           // sequence index n = m / T
        int bidx = nidx >> 4;                // batch b = n / P
        float Kv = fminf(fabsf(curv[bidx]), 10.f);
        float Sv = fminf(fmaxf(ent[bidx], 0.f), 5.f);
        float b1 = sigm(pre[192 + lane] + Wbb[lane]);
        g_beta[m * HEADS + lane]  = sigm(b1 + Kv * cw[lane]);
        float a1 = sigm(pre[196 + lane] + Wab[lane]);
        g_alpha[m * HEADS + lane] = sigm(a1 + Sv * ew[lane]);
    }
}

// ---------------------------------------------------------------------------
// Kernel C: sequential delta-rule scan.
// One block per sequence n (64 blocks x 64 threads).
// Thread (h, i) owns row i of M[h] (16 registers). k/q/v/beta/alpha staged in
// smem in 32-step chunks; per step:
//   Mk_i = sum_j M[i][j] k[j];  c = beta*v_i - alpha*Mk_i;
//   M[i][j] += k[j]*c;          o_i = sum_j M[i][j] q[j]
// ---------------------------------------------------------------------------
#define SCAN_CT 32

__global__ __launch_bounds__(64) void scan_kernel()
{
    const int n   = blockIdx.x;
    const int tid = threadIdx.x;
    const int h   = tid >> 4;
    const int i   = tid & 15;

    __shared__ __align__(16) float ks[SCAN_CT * 64];
    __shared__ __align__(16) float qs[SCAN_CT * 64];
    __shared__ __align__(16) float vs[SCAN_CT * 64];
    __shared__ __align__(16) float os[SCAN_CT * 64];
    __shared__ float bs[SCAN_CT * HEADS];
    __shared__ float as_[SCAN_CT * HEADS];

    float M[16];
#pragma unroll
    for (int j = 0; j < 16; j++) M[j] = 0.f;

    for (int t0 = 0; t0 < TLEN; t0 += SCAN_CT) {
        const size_t base  = ((size_t)n * TLEN + t0) * 64;
        const size_t base2 = ((size_t)n * TLEN + t0) * HEADS;

        // ---- stage chunk ----
        {
            const float4* gk4 = (const float4*)(g_k + base);
            const float4* gq4 = (const float4*)(g_q + base);
            const float4* gv4 = (const float4*)(g_v + base);
            float4* ks4 = (float4*)ks;
            float4* qs4 = (float4*)qs;
            float4* vs4 = (float4*)vs;
#pragma unroll
            for (int idx = tid; idx < SCAN_CT * 16; idx += 64) {
                ks4[idx] = gk4[idx];
                qs4[idx] = gq4[idx];
                vs4[idx] = gv4[idx];
            }
#pragma unroll
            for (int idx = tid; idx < SCAN_CT * HEADS; idx += 64) {
                bs[idx]  = g_beta[base2 + idx];
                as_[idx] = g_alpha[base2 + idx];
            }
        }
        __syncthreads();

        // ---- scan 32 steps ----
        for (int tt = 0; tt < SCAN_CT; tt++) {
            const float* kp = ks + tt * 64 + h * 16;
            float4 k0 = *(const float4*)(kp);
            float4 k1 = *(const float4*)(kp + 4);
            float4 k2 = *(const float4*)(kp + 8);
            float4 k3 = *(const float4*)(kp + 12);
            float kr[16] = {k0.x,k0.y,k0.z,k0.w, k1.x,k1.y,k1.z,k1.w,
                            k2.x,k2.y,k2.z,k2.w, k3.x,k3.y,k3.z,k3.w};

            float s0 = 0.f, s1 = 0.f, s2 = 0.f, s3 = 0.f;
#pragma unroll
            for (int u = 0; u < 4; u++) {
                s0 = fmaf(M[u],      kr[u],      s0);
                s1 = fmaf(M[4 + u],  kr[4 + u],  s1);
                s2 = fmaf(M[8 + u],  kr[8 + u],  s2);
                s3 = fmaf(M[12 + u], kr[12 + u], s3);
            }
            float Mk = (s0 + s1) + (s2 + s3);

            float a  = as_[tt * HEADS + h];
            float b  = bs [tt * HEADS + h];
            float vi = vs [tt * 64 + h * 16 + i];
            float c  = b * vi - a * Mk;

#pragma unroll
            for (int j = 0; j < 16; j++) M[j] = fmaf(kr[j], c, M[j]);

            const float* qp = qs + tt * 64 + h * 16;
            float4 q0 = *(const float4*)(qp);
            float4 q1 = *(const float4*)(qp + 4);
            float4 q2 = *(const float4*)(qp + 8);
            float4 q3 = *(const float4*)(qp + 12);
            float qr[16] = {q0.x,q0.y,q0.z,q0.w, q1.x,q1.y,q1.z,q1.w,
                            q2.x,q2.y,q2.z,q2.w, q3.x,q3.y,q3.z,q3.w};

            float o0 = 0.f, o1 = 0.f, o2 = 0.f, o3 = 0.f;
#pragma unroll
            for (int u = 0; u < 4; u++) {
                o0 = fmaf(M[u],      qr[u],      o0);
                o1 = fmaf(M[4 + u],  qr[4 + u],  o1);
                o2 = fmaf(M[8 + u],  qr[8 + u],  o2);
                o3 = fmaf(M[12 + u], qr[12 + u], o3);
            }
            os[tt * 64 + h * 16 + i] = (o0 + o1) + (o2 + o3);
        }
        __syncthreads();

        // ---- flush o chunk ----
        {
            float4* go4 = (float4*)(g_o + base);
            const float4* os4 = (const float4*)os;
#pragma unroll
            for (int idx = tid; idx < SCAN_CT * 16; idx += 64)
                go4[idx] = os4[idx];
        }
        // next iteration's post-load __syncthreads orders this flush vs. os reuse
    }
}

// ---------------------------------------------------------------------------
// Kernel D: out GEMM  fib = o[131072,64] @ out_w^T[64,192] + out_b,
// with scatter-store to (B,T,P,K) layout.
// BM=64, BN=64, BK=64 (full K), 256 threads, thread tile 4x4
// ---------------------------------------------------------------------------
__global__ __launch_bounds__(256) void gemmD_kernel(const float* __restrict__ ob,
                                                    float* __restrict__ out)
{
    __shared__ __align__(16) float As2[64][64];
    __shared__ __align__(16) float Bs2[64][64];

    const int tid = threadIdx.x;
    const int tx = tid & 15;
    const int ty = tid >> 4;
    const int m0 = blockIdx.y * 64;
    const int n0 = blockIdx.x * 64;

    // load A (g_o): 64x64 = 1024 float4, 4 per thread, store transposed
#pragma unroll
    for (int i = 0; i < 4; i++) {
        int e   = i * 256 + tid;
        int row = e >> 4;
        int kq  = (e & 15) * 4;
        float4 av = *(const float4*)(g_o + (size_t)(m0 + row) * 64 + kq);
        As2[kq+0][row] = av.x; As2[kq+1][row] = av.y;
        As2[kq+2][row] = av.z; As2[kq+3][row] = av.w;
    }
    // load B (g_Bpack2 k-major [64][192])
#pragma unroll
    for (int i = 0; i < 4; i++) {
        int e  = i * 256 + tid;
        int kk = e >> 4;
        int cq = (e & 15) * 4;
        float4 bv = *(const float4*)(g_Bpack2 + (size_t)kk * KOUT + n0 + cq);
        *(float4*)&Bs2[kk][cq] = bv;
    }
    __syncthreads();

    float acc[4][4];
#pragma unroll
    for (int i = 0; i < 4; i++)
#pragma unroll
        for (int j = 0; j < 4; j++) acc[i][j] = 0.f;

#pragma unroll
    for (int kk = 0; kk < 64; kk++) {
        float4 a = *(const float4*)&As2[kk][ty * 4];
        float4 b = *(const float4*)&Bs2[kk][tx * 4];
        float ar[4] = {a.x,a.y,a.z,a.w};
        float br[4] = {b.x,b.y,b.z,b.w};
#pragma unroll
        for (int i = 0; i < 4; i++)
#pragma unroll
            for (int j = 0; j < 4; j++)
                acc[i][j] = fmaf(ar[i], br[j], acc[i][j]);
    }

    // scatter-store: m = n*T + t ; out[((b*T + t)*P + p)*K + col]
    const int nseq = m0 >> 11;          // constant within block (64 | 2048)
    const int tb   = m0 & 2047;
    const int bb   = nseq >> 4;
    const int pp   = nseq & 15;
#pragma unroll
    for (int i = 0; i < 4; i++) {
        int t = tb + ty * 4 + i;
#pragma unroll
        for (int j = 0; j < 4; j++) {
            int col = n0 + tx * 4 + j;
            size_t dst = (((size_t)bb * TLEN + t) * 16 + pp) * KOUT + col;
            out[dst] = acc[i][j] + ob[col];
        }
    }
}

// ---------------------------------------------------------------------------
// launch
// ---------------------------------------------------------------------------
extern "C" void kernel_launch(void* const* d_in, const int* in_sizes, int n_in,
                              void* d_out, int out_size)
{
    const float* joint = (const float*)d_in[0];
    const float* curv  = (const float*)d_in[1];
    const float* ent   = (const float*)d_in[2];
    const float* Wq    = (const float*)d_in[3];
    const float* Wk    = (const float*)d_in[4];
    const float* Wv    = (const float*)d_in[5];
    const float* Wbw   = (const float*)d_in[6];
    const float* Wbb   = (const float*)d_in[7];
    const float* Waw   = (const float*)d_in[8];
    const float* Wab   = (const float*)d_in[9];
    const float* cw    = (const float*)d_in[10];
    const float* ew    = (const float*)d_in[11];
    const float* out_w = (const float*)d_in[12];
    const float* out_b = (const float*)d_in[13];
    const float* lqw   = (const float*)d_in[14];
    const float* lqb   = (const float*)d_in[15];
    const float* lkw   = (const float*)d_in[16];
    const float* lkb   = (const float*)d_in[17];
    float* out = (float*)d_out;

    pack_kernel<<<256, 256>>>(Wq, Wk, Wv, Wbw, Waw, out_w);

    gemmA_kernel<<<dim3(4, M_TOK / A_BM), 256>>>(joint);

    epilogue_kernel<<<M_TOK / 8, 256>>>(curv, ent, Wbb, Wab, cw, ew,
                                        lqw, lqb, lkw, lkb);

    scan_kernel<<<NSEQ, 64>>>();

    gemmD_kernel<<<dim3(KOUT / 64, M_TOK / 64), 256>>>(out_b, out);
}

// round 4
// speedup vs baseline: 1.2848x; 1.2848x over previous
#include <cuda_runtime.h>
#include <cuda_bf16.h>
#include <math.h>

// ---------------------------------------------------------------------------
// B=4, T=2048, P=16, J=256, H=4, D=16, MEM=64, K_OUT=192
// N = B*P = 64 sequences; tokens M_TOK = 131072
// Projection GEMM now emits exactly 192 cols: [0:64) q, [64:128) k, [128:192) v.
// beta/alpha (8 dots of length 256) are computed directly in the epilogue.
// Scan: chunked parallel (C=64, 32 chunks/seq), 3 passes.
// ---------------------------------------------------------------------------

#define M_TOK   131072
#define JDIM    256
#define NPRE    192
#define NSEQ    64
#define TLEN    2048
#define HEADS   4
#define DHEAD   16
#define KOUT    192
#define CCH     64              // chunk length
#define NCHUNK  (TLEN / CCH)    // 32

// -------- scratch (device globals; no allocation allowed) --------
__device__ float g_Bpack [(size_t)JDIM * NPRE];     // [k][o] k-major, 192 cols
__device__ float g_Bpack2[(size_t)64 * KOUT];       // [k][o] for out_w^T
__device__ float g_pre   [(size_t)M_TOK * NPRE];
__device__ float g_q     [(size_t)M_TOK * 64];
__device__ float g_k     [(size_t)M_TOK * 64];
__device__ float g_v     [(size_t)M_TOK * 64];
__device__ float g_beta  [(size_t)M_TOK * HEADS];
__device__ float g_alpha [(size_t)M_TOK * HEADS];
__device__ float g_o     [(size_t)M_TOK * 64];
// chunk operators / states: [(n*NCHUNK + c)*HEADS + h][256]
__device__ float g_T [(size_t)NSEQ * NCHUNK * HEADS * 256];
__device__ float g_U [(size_t)NSEQ * NCHUNK * HEADS * 256];
__device__ float g_S [(size_t)NSEQ * NCHUNK * HEADS * 256];

// ---------------------------------------------------------------------------
// Kernel 0: pack weights into k-major matrices for the GEMMs
// ---------------------------------------------------------------------------
__global__ void pack_kernel(const float* __restrict__ Wq,
                            const float* __restrict__ Wk,
                            const float* __restrict__ Wv,
                            const float* __restrict__ out_w)
{
    int idx = blockIdx.x * blockDim.x + threadIdx.x;
    if (idx < JDIM * NPRE) {
        int k = idx / NPRE;
        int o = idx - k * NPRE;
        float val;
        if      (o < 64)  val = Wq[(size_t)o       * JDIM + k];
        else if (o < 128) val = Wk[(size_t)(o-64)  * JDIM + k];
        else              val = Wv[(size_t)(o-128) * JDIM + k];
        g_Bpack[idx] = val;
    }
    int idx2 = idx - JDIM * NPRE;
    if (idx2 >= 0 && idx2 < 64 * KOUT) {
        int k = idx2 / KOUT;
        int o = idx2 - k * KOUT;
        g_Bpack2[idx2] = out_w[(size_t)o * 64 + k];
    }
}

// ---------------------------------------------------------------------------
// Kernel A: SGEMM  g_pre[131072,192] = x[131072,256] @ g_Bpack[256,192]
// BM=128, BN=64, BK=16, 256 threads, thread tile 8x4. No column guards.
// ---------------------------------------------------------------------------
#define A_BM 128
#define A_BN 64
#define A_BK 16

__global__ __launch_bounds__(256) void gemmA_kernel(const float* __restrict__ A)
{
    __shared__ __align__(16) float As[A_BK][A_BM];
    __shared__ __align__(16) float Bs[A_BK][A_BN];

    const int tid = threadIdx.x;
    const int tx = tid & 15;    // col group (4 cols each)
    const int ty = tid >> 4;    // row group (8 rows each)
    const int m0 = blockIdx.y * A_BM;
    const int n0 = blockIdx.x * A_BN;

    float acc[8][4];
#pragma unroll
    for (int i = 0; i < 8; i++)
#pragma unroll
        for (int j = 0; j < 4; j++) acc[i][j] = 0.f;

    for (int k0 = 0; k0 < JDIM; k0 += A_BK) {
        // A tile: 128 rows x 16 k (512 float4, 2/thread)
#pragma unroll
        for (int i = 0; i < 2; i++) {
            int e   = i * 256 + tid;
            int row = e >> 2;
            int kq  = (e & 3) * 4;
            float4 av = *(const float4*)(A + (size_t)(m0 + row) * JDIM + k0 + kq);
            As[kq+0][row] = av.x; As[kq+1][row] = av.y;
            As[kq+2][row] = av.z; As[kq+3][row] = av.w;
        }
        // B tile: 16 k x 64 cols (256 float4, 1/thread)
        {
            int kk   = tid >> 4;
            int colq = (tid & 15) * 4;
            float4 bv = *(const float4*)(g_Bpack + (size_t)(k0 + kk) * NPRE + n0 + colq);
            *(float4*)&Bs[kk][colq] = bv;
        }
        __syncthreads();

#pragma unroll
        for (int kk = 0; kk < A_BK; kk++) {
            float4 a0 = *(const float4*)&As[kk][ty * 8];
            float4 a1 = *(const float4*)&As[kk][ty * 8 + 4];
            float4 b0 = *(const float4*)&Bs[kk][tx * 4];
            float ar[8] = {a0.x,a0.y,a0.z,a0.w,a1.x,a1.y,a1.z,a1.w};
            float br[4] = {b0.x,b0.y,b0.z,b0.w};
#pragma unroll
            for (int i = 0; i < 8; i++)
#pragma unroll
                for (int j = 0; j < 4; j++)
                    acc[i][j] = fmaf(ar[i], br[j], acc[i][j]);
        }
        __syncthreads();
    }

#pragma unroll
    for (int i = 0; i < 8; i++) {
        int row = m0 + ty * 8 + i;
        float* dst = g_pre + (size_t)row * NPRE + n0 + tx * 4;
        float4 v4 = make_float4(acc[i][0], acc[i][1], acc[i][2], acc[i][3]);
        *(float4*)dst = v4;
    }
}

// ---------------------------------------------------------------------------
// Kernel B: epilogue — LN(q), LN + L2(k), v pass, beta/alpha from x directly.
// One warp per token, 8 tokens/block.
// ---------------------------------------------------------------------------
__device__ __forceinline__ float red16(float x)
{
    x += __shfl_xor_sync(0xffffffffu, x, 8);
    x += __shfl_xor_sync(0xffffffffu, x, 4);
    x += __shfl_xor_sync(0xffffffffu, x, 2);
    x += __shfl_xor_sync(0xffffffffu, x, 1);
    return x;
}
__device__ __forceinline__ float red32(float x)
{
    x += __shfl_xor_sync(0xffffffffu, x, 16);
    x += __shfl_xor_sync(0xffffffffu, x, 8);
    x += __shfl_xor_sync(0xffffffffu, x, 4);
    x += __shfl_xor_sync(0xffffffffu, x, 2);
    x += __shfl_xor_sync(0xffffffffu, x, 1);
    return x;
}
__device__ __forceinline__ float sigm(float x) { return 1.f / (1.f + expf(-x)); }

__global__ __launch_bounds__(256) void epilogue_kernel(
    const float* __restrict__ x,
    const float* __restrict__ curv, const float* __restrict__ ent,
    const float* __restrict__ Wbw,  const float* __restrict__ Wbb,
    const float* __restrict__ Waw,  const float* __restrict__ Wab,
    const float* __restrict__ cw,   const float* __restrict__ ew,
    const float* __restrict__ lqw,  const float* __restrict__ lqb,
    const float* __restrict__ lkw,  const float* __restrict__ lkb)
{
    const int tid  = threadIdx.x;
    const int lane = tid & 31;
    const int w    = tid >> 5;
    const size_t m = (size_t)blockIdx.x * 8 + w;
    const float* pre = g_pre + m * NPRE;
    const int di = lane & 15;

    const float wq = lqw[di], bq = lqb[di];
    const float wk = lkw[di], bk = lkb[di];
    const float inv16 = 1.f / 16.f;

    // ---- q: LayerNorm per head of 16 ----
    float q0 = pre[lane], q1 = pre[32 + lane];
    float mu0 = red16(q0) * inv16, mu1 = red16(q1) * inv16;
    float d0 = q0 - mu0, d1 = q1 - mu1;
    float va0 = red16(d0 * d0) * inv16, va1 = red16(d1 * d1) * inv16;
    g_q[m * 64 + lane]      = d0 / sqrtf(va0 + 1e-5f) * wq + bq;
    g_q[m * 64 + 32 + lane] = d1 / sqrtf(va1 + 1e-5f) * wq + bq;

    // ---- k: LayerNorm + L2 normalize per head ----
    float k0 = pre[64 + lane], k1 = pre[96 + lane];
    float km0 = red16(k0) * inv16, km1 = red16(k1) * inv16;
    float kd0 = k0 - km0, kd1 = k1 - km1;
    float kv0 = red16(kd0 * kd0) * inv16, kv1 = red16(kd1 * kd1) * inv16;
    float kn0 = kd0 / sqrtf(kv0 + 1e-5f) * wk + bk;
    float kn1 = kd1 / sqrtf(kv1 + 1e-5f) * wk + bk;
    float nn0 = red16(kn0 * kn0);
    float nn1 = red16(kn1 * kn1);
    g_k[m * 64 + lane]      = kn0 / fmaxf(sqrtf(nn0), 1e-12f);
    g_k[m * 64 + 32 + lane] = kn1 / fmaxf(sqrtf(nn1), 1e-12f);

    // ---- v passthrough ----
    g_v[m * 64 + lane]      = pre[128 + lane];
    g_v[m * 64 + 32 + lane] = pre[160 + lane];

    // ---- beta/alpha: 8 dots of x[m] (256) with Wbw/Waw rows ----
    const float4* x4 = (const float4*)(x + m * JDIM);
    float4 xv0 = x4[lane * 2];
    float4 xv1 = x4[lane * 2 + 1];
    float par[8];
#pragma unroll
    for (int hh = 0; hh < 8; hh++) {
        const float* wr = (hh < 4) ? (Wbw + (size_t)hh * JDIM)
                                   : (Waw + (size_t)(hh - 4) * JDIM);
        float4 w0 = ((const float4*)wr)[lane * 2];
        float4 w1 = ((const float4*)wr)[lane * 2 + 1];
        float s = xv0.x * w0.x + xv0.y * w0.y + xv0.z * w0.z + xv0.w * w0.w
                + xv1.x * w1.x + xv1.y * w1.y + xv1.z * w1.z + xv1.w * w1.w;
        par[hh] = red32(s);
    }
    if (lane < HEADS) {
        int nidx = (int)(m >> 11);
        int bidx = nidx >> 4;
        float Kv = fminf(fabsf(curv[bidx]), 10.f);
        float Sv = fminf(fmaxf(ent[bidx], 0.f), 5.f);
        float b1 = sigm(par[lane] + Wbb[lane]);
        g_beta[m * HEADS + lane]  = sigm(b1 + Kv * cw[lane]);
        float a1 = sigm(par[4 + lane] + Wab[lane]);
        g_alpha[m * HEADS + lane] = sigm(a1 + Sv * ew[lane]);
    }
}

// ---------------------------------------------------------------------------
// Scan pass 1: per chunk, build T = prod A_t and U = sum B_t prod A_s.
// A_t = I - alpha k k^T ; B_t = beta v k^T. Block = (n, c), 64 threads (h,i).
// ---------------------------------------------------------------------------
__global__ __launch_bounds__(64) void scan_phase1()
{
    const int n   = blockIdx.x;
    const int c   = blockIdx.y;
    const int tid = threadIdx.x;
    const int h   = tid >> 4;
    const int i   = tid & 15;

    __shared__ __align__(16) float ks[CCH * 64];
    __shared__ __align__(16) float vs[CCH * 64];
    __shared__ float bs[CCH * HEADS];
    __shared__ float as_[CCH * HEADS];

    const size_t base  = ((size_t)n * TLEN + (size_t)c * CCH) * 64;
    const size_t base2 = ((size_t)n * TLEN + (size_t)c * CCH) * HEADS;
    {
        const float4* gk4 = (const float4*)(g_k + base);
        const float4* gv4 = (const float4*)(g_v + base);
#pragma unroll
        for (int idx = tid; idx < CCH * 16; idx += 64) {
            ((float4*)ks)[idx] = gk4[idx];
            ((float4*)vs)[idx] = gv4[idx];
        }
#pragma unroll
        for (int idx = tid; idx < CCH * HEADS; idx += 64) {
            bs[idx]  = g_beta[base2 + idx];
            as_[idx] = g_alpha[base2 + idx];
        }
    }
    __syncthreads();

    float Tr[16], Ur[16];
#pragma unroll
    for (int j = 0; j < 16; j++) { Tr[j] = (j == i) ? 1.f : 0.f; Ur[j] = 0.f; }

    for (int tt = 0; tt < CCH; tt++) {
        const float* kp = ks + tt * 64 + h * 16;
        float4 k0 = *(const float4*)(kp);
        float4 k1 = *(const float4*)(kp + 4);
        float4 k2 = *(const float4*)(kp + 8);
        float4 k3 = *(const float4*)(kp + 12);
        float kr[16] = {k0.x,k0.y,k0.z,k0.w, k1.x,k1.y,k1.z,k1.w,
                        k2.x,k2.y,k2.z,k2.w, k3.x,k3.y,k3.z,k3.w};

        float t0=0.f,t1=0.f,t2=0.f,t3=0.f, u0=0.f,u1=0.f,u2=0.f,u3=0.f;
#pragma unroll
        for (int u = 0; u < 4; u++) {
            t0 = fmaf(Tr[u],     kr[u],     t0);
            t1 = fmaf(Tr[4+u],   kr[4+u],   t1);
            t2 = fmaf(Tr[8+u],   kr[8+u],   t2);
            t3 = fmaf(Tr[12+u],  kr[12+u],  t3);
            u0 = fmaf(Ur[u],     kr[u],     u0);
            u1 = fmaf(Ur[4+u],   kr[4+u],   u1);
            u2 = fmaf(Ur[8+u],   kr[8+u],   u2);
            u3 = fmaf(Ur[12+u],  kr[12+u],  u3);
        }
        float Tk = (t0 + t1) + (t2 + t3);
        float Uk = (u0 + u1) + (u2 + u3);

        float a  = as_[tt * HEADS + h];
        float b  = bs [tt * HEADS + h];
        float vi = vs [tt * 64 + h * 16 + i];
        float cT = -a * Tk;
        float cU = b * vi - a * Uk;

#pragma unroll
        for (int j = 0; j < 16; j++) {
            Tr[j] = fmaf(kr[j], cT, Tr[j]);
            Ur[j] = fmaf(kr[j], cU, Ur[j]);
        }
    }

    float* Td = g_T + ((size_t)(n * NCHUNK + c) * HEADS + h) * 256 + i * 16;
    float* Ud = g_U + ((size_t)(n * NCHUNK + c) * HEADS + h) * 256 + i * 16;
#pragma unroll
    for (int j = 0; j < 4; j++) {
        *(float4*)(Td + 4*j) = make_float4(Tr[4*j], Tr[4*j+1], Tr[4*j+2], Tr[4*j+3]);
        *(float4*)(Ud + 4*j) = make_float4(Ur[4*j], Ur[4*j+1], Ur[4*j+2], Ur[4*j+3]);
    }
}

// ---------------------------------------------------------------------------
// Scan pass 2: compose chunk operators sequentially per (n,h):
//   S_0 = 0 ; S_{c+1} = S_c T_c + U_c ; store S_c (state at chunk start).
// Block = n (64 blocks), 64 threads (h,i).
// ---------------------------------------------------------------------------
__global__ __launch_bounds__(64) void scan_phase2()
{
    const int n   = blockIdx.x;
    const int tid = threadIdx.x;
    const int h   = tid >> 4;
    const int i   = tid & 15;

    __shared__ __align__(16) float Ts[HEADS * 256];
    __shared__ __align__(16) float Us[HEADS * 256];

    float Sr[16];
#pragma unroll
    for (int j = 0; j < 16; j++) Sr[j] = 0.f;

    for (int c = 0; c < NCHUNK; c++) {
        const size_t ob = (size_t)(n * NCHUNK + c) * HEADS * 256;
        const float4* Tg = (const float4*)(g_T + ob);
        const float4* Ug = (const float4*)(g_U + ob);
#pragma unroll
        for (int idx = tid; idx < 256; idx += 64) {
            ((float4*)Ts)[idx] = Tg[idx];
            ((float4*)Us)[idx] = Ug[idx];
        }
        // store S (state at start of chunk c)
        float* Sd = g_S + ob + (size_t)h * 256 + i * 16;
#pragma unroll
        for (int j = 0; j < 4; j++)
            *(float4*)(Sd + 4*j) = make_float4(Sr[4*j], Sr[4*j+1], Sr[4*j+2], Sr[4*j+3]);
        __syncthreads();

        float Sn[16];
        const float* Uh = Us + h * 256 + i * 16;
#pragma unroll
        for (int j = 0; j < 16; j++) Sn[j] = Uh[j];
        const float* Th = Ts + h * 256;
#pragma unroll
        for (int u = 0; u < 16; u++) {
            float su = Sr[u];
            const float* Tu = Th + u * 16;
#pragma unroll
            for (int j = 0; j < 16; j++) Sn[j] = fmaf(su, Tu[j], Sn[j]);
        }
#pragma unroll
        for (int j = 0; j < 16; j++) Sr[j] = Sn[j];
        __syncthreads();
    }
}

// ---------------------------------------------------------------------------
// Scan pass 3: per chunk, load start state S_c and replay 64 steps, computing
// outputs o_t = M_t q_t. Staged in two 32-step halves (smem budget).
// ---------------------------------------------------------------------------
__global__ __launch_bounds__(64) void scan_phase3()
{
    const int n   = blockIdx.x;
    const int c   = blockIdx.y;
    const int tid = threadIdx.x;
    const int h   = tid >> 4;
    const int i   = tid & 15;

    __shared__ __align__(16) float ks[32 * 64];
    __shared__ __align__(16) float qs[32 * 64];
    __shared__ __align__(16) float vs[32 * 64];
    __shared__ float bs[32 * HEADS];
    __shared__ float as_[32 * HEADS];

    float M[16];
    {
        const float* Sg = g_S + ((size_t)(n * NCHUNK + c) * HEADS + h) * 256 + i * 16;
#pragma unroll
        for (int j = 0; j < 4; j++) {
            float4 s4 = *(const float4*)(Sg + 4*j);
            M[4*j] = s4.x; M[4*j+1] = s4.y; M[4*j+2] = s4.z; M[4*j+3] = s4.w;
        }
    }

    for (int half = 0; half < 2; half++) {
        const size_t base  = ((size_t)n * TLEN + (size_t)c * CCH + half * 32) * 64;
        const size_t base2 = ((size_t)n * TLEN + (size_t)c * CCH + half * 32) * HEADS;
        {
            const float4* gk4 = (const float4*)(g_k + base);
            const float4* gq4 = (const float4*)(g_q + base);
            const float4* gv4 = (const float4*)(g_v + base);
#pragma unroll
            for (int idx = tid; idx < 32 * 16; idx += 64) {
                ((float4*)ks)[idx] = gk4[idx];
                ((float4*)qs)[idx] = gq4[idx];
                ((float4*)vs)[idx] = gv4[idx];
            }
#pragma unroll
            for (int idx = tid; idx < 32 * HEADS; idx += 64) {
                bs[idx]  = g_beta[base2 + idx];
                as_[idx] = g_alpha[base2 + idx];
            }
        }
        __syncthreads();

        for (int tt = 0; tt < 32; tt++) {
            const float* kp = ks + tt * 64 + h * 16;
            float4 k0 = *(const float4*)(kp);
            float4 k1 = *(const float4*)(kp + 4);
            float4 k2 = *(const float4*)(kp + 8);
            float4 k3 = *(const float4*)(kp + 12);
            float kr[16] = {k0.x,k0.y,k0.z,k0.w, k1.x,k1.y,k1.z,k1.w,
                            k2.x,k2.y,k2.z,k2.w, k3.x,k3.y,k3.z,k3.w};

            float s0=0.f,s1=0.f,s2=0.f,s3=0.f;
#pragma unroll
            for (int u = 0; u < 4; u++) {
                s0 = fmaf(M[u],     kr[u],     s0);
                s1 = fmaf(M[4+u],   kr[4+u],   s1);
                s2 = fmaf(M[8+u],   kr[8+u],   s2);
                s3 = fmaf(M[12+u],  kr[12+u],  s3);
            }
            float Mk = (s0 + s1) + (s2 + s3);

            float a  = as_[tt * HEADS + h];
            float b  = bs [tt * HEADS + h];
            float vi = vs [tt * 64 + h * 16 + i];
            float cc = b * vi - a * Mk;

#pragma unroll
            for (int j = 0; j < 16; j++) M[j] = fmaf(kr[j], cc, M[j]);

            const float* qp = qs + tt * 64 + h * 16;
            float4 q0 = *(const float4*)(qp);
            float4 q1 = *(const float4*)(qp + 4);
            float4 q2 = *(const float4*)(qp + 8);
            float4 q3 = *(const float4*)(qp + 12);
            float qr[16] = {q0.x,q0.y,q0.z,q0.w, q1.x,q1.y,q1.z,q1.w,
                            q2.x,q2.y,q2.z,q2.w, q3.x,q3.y,q3.z,q3.w};

            float o0=0.f,o1=0.f,o2=0.f,o3=0.f;
#pragma unroll
            for (int u = 0; u < 4; u++) {
                o0 = fmaf(M[u],     qr[u],     o0);
                o1 = fmaf(M[4+u],   qr[4+u],   o1);
                o2 = fmaf(M[8+u],   qr[8+u],   o2);
                o3 = fmaf(M[12+u],  qr[12+u],  o3);
            }
            g_o[base + tt * 64 + h * 16 + i] = (o0 + o1) + (o2 + o3);
        }
        __syncthreads();
    }
}

// ---------------------------------------------------------------------------
// Kernel D: out GEMM  fib = o[131072,64] @ out_w^T[64,192] + out_b,
// scatter-store to (B,T,P,K). BM=64, BN=64, BK=64, 256 threads, 4x4 tile.
// ---------------------------------------------------------------------------
__global__ __launch_bounds__(256) void gemmD_kernel(const float* __restrict__ ob,
                                                    float* __restrict__ out)
{
    __shared__ __align__(16) float As2[64][64];
    __shared__ __align__(16) float Bs2[64][64];

    const int tid = threadIdx.x;
    const int tx = tid & 15;
    const int ty = tid >> 4;
    const int m0 = blockIdx.y * 64;
    const int n0 = blockIdx.x * 64;

#pragma unroll
    for (int i = 0; i < 4; i++) {
        int e   = i * 256 + tid;
        int row = e >> 4;
        int kq  = (e & 15) * 4;
        float4 av = *(const float4*)(g_o + (size_t)(m0 + row) * 64 + kq);
        As2[kq+0][row] = av.x; As2[kq+1][row] = av.y;
        As2[kq+2][row] = av.z; As2[kq+3][row] = av.w;
    }
#pragma unroll
    for (int i = 0; i < 4; i++) {
        int e  = i * 256 + tid;
        int kk = e >> 4;
        int cq = (e & 15) * 4;
        float4 bv = *(const float4*)(g_Bpack2 + (size_t)kk * KOUT + n0 + cq);
        *(float4*)&Bs2[kk][cq] = bv;
    }
    __syncthreads();

    float acc[4][4];
#pragma unroll
    for (int i = 0; i < 4; i++)
#pragma unroll
        for (int j = 0; j < 4; j++) acc[i][j] = 0.f;

#pragma unroll
    for (int kk = 0; kk < 64; kk++) {
        float4 a = *(const float4*)&As2[kk][ty * 4];
        float4 b = *(const float4*)&Bs2[kk][tx * 4];
        float ar[4] = {a.x,a.y,a.z,a.w};
        float br[4] = {b.x,b.y,b.z,b.w};
#pragma unroll
        for (int i = 0; i < 4; i++)
#pragma unroll
            for (int j = 0; j < 4; j++)
                acc[i][j] = fmaf(ar[i], br[j], acc[i][j]);
    }

    const int nseq = m0 >> 11;
    const int tb   = m0 & 2047;
    const int bb   = nseq >> 4;
    const int pp   = nseq & 15;
#pragma unroll
    for (int i = 0; i < 4; i++) {
        int t = tb + ty * 4 + i;
#pragma unroll
        for (int j = 0; j < 4; j++) {
            int col = n0 + tx * 4 + j;
            size_t dst = (((size_t)bb * TLEN + t) * 16 + pp) * KOUT + col;
            out[dst] = acc[i][j] + ob[col];
        }
    }
}

// ---------------------------------------------------------------------------
// launch
// ---------------------------------------------------------------------------
extern "C" void kernel_launch(void* const* d_in, const int* in_sizes, int n_in,
                              void* d_out, int out_size)
{
    const float* joint = (const float*)d_in[0];
    const float* curv  = (const float*)d_in[1];
    const float* ent   = (const float*)d_in[2];
    const float* Wq    = (const float*)d_in[3];
    const float* Wk    = (const float*)d_in[4];
    const float* Wv    = (const float*)d_in[5];
    const float* Wbw   = (const float*)d_in[6];
    const float* Wbb   = (const float*)d_in[7];
    const float* Waw   = (const float*)d_in[8];
    const float* Wab   = (const float*)d_in[9];
    const float* cw    = (const float*)d_in[10];
    const float* ew    = (const float*)d_in[11];
    const float* out_w = (const float*)d_in[12];
    const float* out_b = (const float*)d_in[13];
    const float* lqw   = (const float*)d_in[14];
    const float* lqb   = (const float*)d_in[15];
    const float* lkw   = (const float*)d_in[16];
    const float* lkb   = (const float*)d_in[17];
    float* out = (float*)d_out;

    pack_kernel<<<256, 256>>>(Wq, Wk, Wv, out_w);

    gemmA_kernel<<<dim3(NPRE / A_BN, M_TOK / A_BM), 256>>>(joint);

    epilogue_kernel<<<M_TOK / 8, 256>>>(joint, curv, ent, Wbw, Wbb, Waw, Wab,
                                        cw, ew, lqw, lqb, lkw, lkb);

    scan_phase1<<<dim3(NSEQ, NCHUNK), 64>>>();
    scan_phase2<<<NSEQ, 64>>>();
    scan_phase3<<<dim3(NSEQ, NCHUNK), 64>>>();

    gemmD_kernel<<<dim3(KOUT / 64, M_TOK / 64), 256>>>(out_b, out);
}

// round 5
// speedup vs baseline: 2.0677x; 1.6093x over previous
#include <cuda_runtime.h>
#include <cuda_bf16.h>
#include <math.h>

// ---------------------------------------------------------------------------
// B=4, T=2048, P=16, J=256, H=4, D=16, MEM=64, K_OUT=192
// N = B*P = 64 sequences; tokens M_TOK = 131072
// gemmA/gemmD now run on tensor cores via tf32 mma.sync.m16n8k8.
// Scan: chunked parallel (C=64, 32 chunks/seq), 3 passes (unchanged).
// ---------------------------------------------------------------------------

#define M_TOK   131072
#define JDIM    256
#define NPRE    192
#define NSEQ    64
#define TLEN    2048
#define HEADS   4
#define DHEAD   16
#define KOUT    192
#define CCH     64
#define NCHUNK  (TLEN / CCH)

// -------- scratch (device globals; no allocation allowed) --------
__device__ float g_Bpack [(size_t)JDIM * NPRE];     // [k][o] k-major, tf32-rounded
__device__ float g_Bpack2[(size_t)64 * KOUT];       // [k][o], tf32-rounded
__device__ float g_pre   [(size_t)M_TOK * NPRE];
__device__ float g_q     [(size_t)M_TOK * 64];
__device__ float g_k     [(size_t)M_TOK * 64];
__device__ float g_v     [(size_t)M_TOK * 64];
__device__ float g_beta  [(size_t)M_TOK * HEADS];
__device__ float g_alpha [(size_t)M_TOK * HEADS];
__device__ float g_o     [(size_t)M_TOK * 64];
__device__ float g_T [(size_t)NSEQ * NCHUNK * HEADS * 256];
__device__ float g_U [(size_t)NSEQ * NCHUNK * HEADS * 256];
__device__ float g_S [(size_t)NSEQ * NCHUNK * HEADS * 256];

// ---- tf32 helpers ----
__device__ __forceinline__ float tf32r(float x)
{
    unsigned u;
    asm("cvt.rna.tf32.f32 %0, %1;" : "=r"(u) : "f"(x));
    return __uint_as_float(u);
}
__device__ __forceinline__ unsigned fu(float x) { return __float_as_uint(x); }

#define MMA_TF32(c, a, b)                                                     \
    asm volatile("mma.sync.aligned.m16n8k8.row.col.f32.tf32.tf32.f32 "        \
                 "{%0,%1,%2,%3}, {%4,%5,%6,%7}, {%8,%9}, {%0,%1,%2,%3};"      \
                 : "+f"((c)[0]), "+f"((c)[1]), "+f"((c)[2]), "+f"((c)[3])     \
                 : "r"((a)[0]), "r"((a)[1]), "r"((a)[2]), "r"((a)[3]),        \
                   "r"((b)[0]), "r"((b)[1]))

// ---------------------------------------------------------------------------
// Kernel 0: pack weights (k-major) + round to tf32
// ---------------------------------------------------------------------------
__global__ void pack_kernel(const float* __restrict__ Wq,
                            const float* __restrict__ Wk,
                            const float* __restrict__ Wv,
                            const float* __restrict__ out_w)
{
    int idx = blockIdx.x * blockDim.x + threadIdx.x;
    if (idx < JDIM * NPRE) {
        int k = idx / NPRE;
        int o = idx - k * NPRE;
        float val;
        if      (o < 64)  val = Wq[(size_t)o       * JDIM + k];
        else if (o < 128) val = Wk[(size_t)(o-64)  * JDIM + k];
        else              val = Wv[(size_t)(o-128) * JDIM + k];
        g_Bpack[idx] = tf32r(val);
    }
    int idx2 = idx - JDIM * NPRE;
    if (idx2 >= 0 && idx2 < 64 * KOUT) {
        int k = idx2 / KOUT;
        int o = idx2 - k * KOUT;
        g_Bpack2[idx2] = tf32r(out_w[(size_t)o * 64 + k]);
    }
}

// ---------------------------------------------------------------------------
// Kernel A (tf32 tensor): g_pre[131072,192] = x[131072,256] @ g_Bpack[256,192]
// BM=128, BN=64, BK=32. 128 threads = 4 warps (2M x 2N), warp tile 64x32.
// SMEM strides 36/68 -> conflict-free fragment loads.
// ---------------------------------------------------------------------------
#define ASTR 36
#define BSTR 68

__global__ __launch_bounds__(128) void gemmA_kernel(const float* __restrict__ A)
{
    __shared__ __align__(16) float As[128][ASTR];
    __shared__ __align__(16) float Bs[32][BSTR];

    const int tid  = threadIdx.x;
    const int lane = tid & 31;
    const int wid  = tid >> 5;
    const int g    = lane >> 2;    // 0..7
    const int t    = lane & 3;     // 0..3
    const int wm   = (wid >> 1) * 64;
    const int wn   = (wid & 1) * 32;
    const int m0   = blockIdx.y * 128;
    const int n0   = blockIdx.x * 64;

    float acc[4][4][4];
#pragma unroll
    for (int i = 0; i < 4; i++)
#pragma unroll
        for (int j = 0; j < 4; j++)
#pragma unroll
            for (int r = 0; r < 4; r++) acc[i][j][r] = 0.f;

    for (int k0 = 0; k0 < JDIM; k0 += 32) {
        // A tile: 128 x 32, convert to tf32-RN
#pragma unroll
        for (int i = 0; i < 8; i++) {
            int e   = i * 128 + tid;
            int row = e >> 3;
            int cq  = (e & 7) * 4;
            float4 av = *(const float4*)(A + (size_t)(m0 + row) * JDIM + k0 + cq);
            float4 tv = make_float4(tf32r(av.x), tf32r(av.y), tf32r(av.z), tf32r(av.w));
            *(float4*)&As[row][cq] = tv;
        }
        // B tile: 32 x 64 (already tf32)
#pragma unroll
        for (int i = 0; i < 4; i++) {
            int e  = i * 128 + tid;
            int kk = e >> 4;
            int cq = (e & 15) * 4;
            float4 bv = *(const float4*)(g_Bpack + (size_t)(k0 + kk) * NPRE + n0 + cq);
            *(float4*)&Bs[kk][cq] = bv;
        }
        __syncthreads();

#pragma unroll
        for (int ks = 0; ks < 4; ks++) {
            const int kb = ks * 8;
            unsigned a[4][4], b[4][2];
#pragma unroll
            for (int mt = 0; mt < 4; mt++) {
                int r = wm + mt * 16 + g;
                a[mt][0] = fu(As[r][kb + t]);
                a[mt][1] = fu(As[r + 8][kb + t]);
                a[mt][2] = fu(As[r][kb + t + 4]);
                a[mt][3] = fu(As[r + 8][kb + t + 4]);
            }
#pragma unroll
            for (int nt = 0; nt < 4; nt++) {
                int n = wn + nt * 8 + g;
                b[nt][0] = fu(Bs[kb + t][n]);
                b[nt][1] = fu(Bs[kb + t + 4][n]);
            }
#pragma unroll
            for (int mt = 0; mt < 4; mt++)
#pragma unroll
                for (int nt = 0; nt < 4; nt++)
                    MMA_TF32(acc[mt][nt], a[mt], b[nt]);
        }
        __syncthreads();
    }

    // store: c0,c1 at (row, 2t), c2,c3 at (row+8, 2t) -> coalesced float2
#pragma unroll
    for (int mt = 0; mt < 4; mt++) {
#pragma unroll
        for (int nt = 0; nt < 4; nt++) {
            int row = m0 + wm + mt * 16 + g;
            int col = n0 + wn + nt * 8 + 2 * t;
            *(float2*)(g_pre + (size_t)row * NPRE + col) =
                make_float2(acc[mt][nt][0], acc[mt][nt][1]);
            *(float2*)(g_pre + (size_t)(row + 8) * NPRE + col) =
                make_float2(acc[mt][nt][2], acc[mt][nt][3]);
        }
    }
}

// ---------------------------------------------------------------------------
// Kernel B: epilogue — LN(q), LN+L2(k), v pass, beta/alpha from x directly.
// ---------------------------------------------------------------------------
__device__ __forceinline__ float red16(float x)
{
    x += __shfl_xor_sync(0xffffffffu, x, 8);
    x += __shfl_xor_sync(0xffffffffu, x, 4);
    x += __shfl_xor_sync(0xffffffffu, x, 2);
    x += __shfl_xor_sync(0xffffffffu, x, 1);
    return x;
}
__device__ __forceinline__ float red32(float x)
{
    x += __shfl_xor_sync(0xffffffffu, x, 16);
    x += __shfl_xor_sync(0xffffffffu, x, 8);
    x += __shfl_xor_sync(0xffffffffu, x, 4);
    x += __shfl_xor_sync(0xffffffffu, x, 2);
    x += __shfl_xor_sync(0xffffffffu, x, 1);
    return x;
}
__device__ __forceinline__ float sigm(float x) { return 1.f / (1.f + expf(-x)); }

__global__ __launch_bounds__(256) void epilogue_kernel(
    const float* __restrict__ x,
    const float* __restrict__ curv, const float* __restrict__ ent,
    const float* __restrict__ Wbw,  const float* __restrict__ Wbb,
    const float* __restrict__ Waw,  const float* __restrict__ Wab,
    const float* __restrict__ cw,   const float* __restrict__ ew,
    const float* __restrict__ lqw,  const float* __restrict__ lqb,
    const float* __restrict__ lkw,  const float* __restrict__ lkb)
{
    const int tid  = threadIdx.x;
    const int lane = tid & 31;
    const int w    = tid >> 5;
    const size_t m = (size_t)blockIdx.x * 8 + w;
    const float* pre = g_pre + m * NPRE;
    const int di = lane & 15;

    const float wq = lqw[di], bq = lqb[di];
    const float wk = lkw[di], bk = lkb[di];
    const float inv16 = 1.f / 16.f;

    float q0 = pre[lane], q1 = pre[32 + lane];
    float mu0 = red16(q0) * inv16, mu1 = red16(q1) * inv16;
    float d0 = q0 - mu0, d1 = q1 - mu1;
    float va0 = red16(d0 * d0) * inv16, va1 = red16(d1 * d1) * inv16;
    g_q[m * 64 + lane]      = d0 / sqrtf(va0 + 1e-5f) * wq + bq;
    g_q[m * 64 + 32 + lane] = d1 / sqrtf(va1 + 1e-5f) * wq + bq;

    float k0 = pre[64 + lane], k1 = pre[96 + lane];
    float km0 = red16(k0) * inv16, km1 = red16(k1) * inv16;
    float kd0 = k0 - km0, kd1 = k1 - km1;
    float kv0 = red16(kd0 * kd0) * inv16, kv1 = red16(kd1 * kd1) * inv16;
    float kn0 = kd0 / sqrtf(kv0 + 1e-5f) * wk + bk;
    float kn1 = kd1 / sqrtf(kv1 + 1e-5f) * wk + bk;
    float nn0 = red16(kn0 * kn0);
    float nn1 = red16(kn1 * kn1);
    g_k[m * 64 + lane]      = kn0 / fmaxf(sqrtf(nn0), 1e-12f);
    g_k[m * 64 + 32 + lane] = kn1 / fmaxf(sqrtf(nn1), 1e-12f);

    g_v[m * 64 + lane]      = pre[128 + lane];
    g_v[m * 64 + 32 + lane] = pre[160 + lane];

    const float4* x4 = (const float4*)(x + m * JDIM);
    float4 xv0 = x4[lane * 2];
    float4 xv1 = x4[lane * 2 + 1];
    float par[8];
#pragma unroll
    for (int hh = 0; hh < 8; hh++) {
        const float* wr = (hh < 4) ? (Wbw + (size_t)hh * JDIM)
                                   : (Waw + (size_t)(hh - 4) * JDIM);
        float4 w0 = ((const float4*)wr)[lane * 2];
        float4 w1 = ((const float4*)wr)[lane * 2 + 1];
        float s = xv0.x * w0.x + xv0.y * w0.y + xv0.z * w0.z + xv0.w * w0.w
                + xv1.x * w1.x + xv1.y * w1.y + xv1.z * w1.z + xv1.w * w1.w;
        par[hh] = red32(s);
    }
    if (lane < HEADS) {
        int nidx = (int)(m >> 11);
        int bidx = nidx >> 4;
        float Kv = fminf(fabsf(curv[bidx]), 10.f);
        float Sv = fminf(fmaxf(ent[bidx], 0.f), 5.f);
        float b1 = sigm(par[lane] + Wbb[lane]);
        g_beta[m * HEADS + lane]  = sigm(b1 + Kv * cw[lane]);
        float a1 = sigm(par[4 + lane] + Wab[lane]);
        g_alpha[m * HEADS + lane] = sigm(a1 + Sv * ew[lane]);
    }
}

// ---------------------------------------------------------------------------
// Scan pass 1: per chunk, build T = prod A_t and U = sum B_t prod A_s.
// ---------------------------------------------------------------------------
__global__ __launch_bounds__(64) void scan_phase1()
{
    const int n   = blockIdx.x;
    const int c   = blockIdx.y;
    const int tid = threadIdx.x;
    const int h   = tid >> 4;
    const int i   = tid & 15;

    __shared__ __align__(16) float ks[CCH * 64];
    __shared__ __align__(16) float vs[CCH * 64];
    __shared__ float bs[CCH * HEADS];
    __shared__ float as_[CCH * HEADS];

    const size_t base  = ((size_t)n * TLEN + (size_t)c * CCH) * 64;
    const size_t base2 = ((size_t)n * TLEN + (size_t)c * CCH) * HEADS;
    {
        const float4* gk4 = (const float4*)(g_k + base);
        const float4* gv4 = (const float4*)(g_v + base);
#pragma unroll
        for (int idx = tid; idx < CCH * 16; idx += 64) {
            ((float4*)ks)[idx] = gk4[idx];
            ((float4*)vs)[idx] = gv4[idx];
        }
#pragma unroll
        for (int idx = tid; idx < CCH * HEADS; idx += 64) {
            bs[idx]  = g_beta[base2 + idx];
            as_[idx] = g_alpha[base2 + idx];
        }
    }
    __syncthreads();

    float Tr[16], Ur[16];
#pragma unroll
    for (int j = 0; j < 16; j++) { Tr[j] = (j == i) ? 1.f : 0.f; Ur[j] = 0.f; }

    for (int tt = 0; tt < CCH; tt++) {
        const float* kp = ks + tt * 64 + h * 16;
        float4 k0 = *(const float4*)(kp);
        float4 k1 = *(const float4*)(kp + 4);
        float4 k2 = *(const float4*)(kp + 8);
        float4 k3 = *(const float4*)(kp + 12);
        float kr[16] = {k0.x,k0.y,k0.z,k0.w, k1.x,k1.y,k1.z,k1.w,
                        k2.x,k2.y,k2.z,k2.w, k3.x,k3.y,k3.z,k3.w};

        float t0=0.f,t1=0.f,t2=0.f,t3=0.f, u0=0.f,u1=0.f,u2=0.f,u3=0.f;
#pragma unroll
        for (int u = 0; u < 4; u++) {
            t0 = fmaf(Tr[u],     kr[u],     t0);
            t1 = fmaf(Tr[4+u],   kr[4+u],   t1);
            t2 = fmaf(Tr[8+u],   kr[8+u],   t2);
            t3 = fmaf(Tr[12+u],  kr[12+u],  t3);
            u0 = fmaf(Ur[u],     kr[u],     u0);
            u1 = fmaf(Ur[4+u],   kr[4+u],   u1);
            u2 = fmaf(Ur[8+u],   kr[8+u],   u2);
            u3 = fmaf(Ur[12+u],  kr[12+u],  u3);
        }
        float Tk = (t0 + t1) + (t2 + t3);
        float Uk = (u0 + u1) + (u2 + u3);

        float a  = as_[tt * HEADS + h];
        float b  = bs [tt * HEADS + h];
        float vi = vs [tt * 64 + h * 16 + i];
        float cT = -a * Tk;
        float cU = b * vi - a * Uk;

#pragma unroll
        for (int j = 0; j < 16; j++) {
            Tr[j] = fmaf(kr[j], cT, Tr[j]);
            Ur[j] = fmaf(kr[j], cU, Ur[j]);
        }
    }

    float* Td = g_T + ((size_t)(n * NCHUNK + c) * HEADS + h) * 256 + i * 16;
    float* Ud = g_U + ((size_t)(n * NCHUNK + c) * HEADS + h) * 256 + i * 16;
#pragma unroll
    for (int j = 0; j < 4; j++) {
        *(float4*)(Td + 4*j) = make_float4(Tr[4*j], Tr[4*j+1], Tr[4*j+2], Tr[4*j+3]);
        *(float4*)(Ud + 4*j) = make_float4(Ur[4*j], Ur[4*j+1], Ur[4*j+2], Ur[4*j+3]);
    }
}

// ---------------------------------------------------------------------------
// Scan pass 2: compose chunk operators sequentially per (n,h).
// ---------------------------------------------------------------------------
__global__ __launch_bounds__(64) void scan_phase2()
{
    const int n   = blockIdx.x;
    const int tid = threadIdx.x;
    const int h   = tid >> 4;
    const int i   = tid & 15;

    __shared__ __align__(16) float Ts[HEADS * 256];
    __shared__ __align__(16) float Us[HEADS * 256];

    float Sr[16];
#pragma unroll
    for (int j = 0; j < 16; j++) Sr[j] = 0.f;

    for (int c = 0; c < NCHUNK; c++) {
        const size_t ob = (size_t)(n * NCHUNK + c) * HEADS * 256;
        const float4* Tg = (const float4*)(g_T + ob);
        const float4* Ug = (const float4*)(g_U + ob);
#pragma unroll
        for (int idx = tid; idx < 256; idx += 64) {
            ((float4*)Ts)[idx] = Tg[idx];
            ((float4*)Us)[idx] = Ug[idx];
        }
        float* Sd = g_S + ob + (size_t)h * 256 + i * 16;
#pragma unroll
        for (int j = 0; j < 4; j++)
            *(float4*)(Sd + 4*j) = make_float4(Sr[4*j], Sr[4*j+1], Sr[4*j+2], Sr[4*j+3]);
        __syncthreads();

        float Sn[16];
        const float* Uh = Us + h * 256 + i * 16;
#pragma unroll
        for (int j = 0; j < 16; j++) Sn[j] = Uh[j];
        const float* Th = Ts + h * 256;
#pragma unroll
        for (int u = 0; u < 16; u++) {
            float su = Sr[u];
            const float* Tu = Th + u * 16;
#pragma unroll
            for (int j = 0; j < 16; j++) Sn[j] = fmaf(su, Tu[j], Sn[j]);
        }
#pragma unroll
        for (int j = 0; j < 16; j++) Sr[j] = Sn[j];
        __syncthreads();
    }
}

// ---------------------------------------------------------------------------
// Scan pass 3: replay each chunk from its start state, emit outputs.
// ---------------------------------------------------------------------------
__global__ __launch_bounds__(64) void scan_phase3()
{
    const int n   = blockIdx.x;
    const int c   = blockIdx.y;
    const int tid = threadIdx.x;
    const int h   = tid >> 4;
    const int i   = tid & 15;

    __shared__ __align__(16) float ks[32 * 64];
    __shared__ __align__(16) float qs[32 * 64];
    __shared__ __align__(16) float vs[32 * 64];
    __shared__ float bs[32 * HEADS];
    __shared__ float as_[32 * HEADS];

    float M[16];
    {
        const float* Sg = g_S + ((size_t)(n * NCHUNK + c) * HEADS + h) * 256 + i * 16;
#pragma unroll
        for (int j = 0; j < 4; j++) {
            float4 s4 = *(const float4*)(Sg + 4*j);
            M[4*j] = s4.x; M[4*j+1] = s4.y; M[4*j+2] = s4.z; M[4*j+3] = s4.w;
        }
    }

    for (int half = 0; half < 2; half++) {
        const size_t base  = ((size_t)n * TLEN + (size_t)c * CCH + half * 32) * 64;
        const size_t base2 = ((size_t)n * TLEN + (size_t)c * CCH + half * 32) * HEADS;
        {
            const float4* gk4 = (const float4*)(g_k + base);
            const float4* gq4 = (const float4*)(g_q + base);
            const float4* gv4 = (const float4*)(g_v + base);
#pragma unroll
            for (int idx = tid; idx < 32 * 16; idx += 64) {
                ((float4*)ks)[idx] = gk4[idx];
                ((float4*)qs)[idx] = gq4[idx];
                ((float4*)vs)[idx] = gv4[idx];
            }
#pragma unroll
            for (int idx = tid; idx < 32 * HEADS; idx += 64) {
                bs[idx]  = g_beta[base2 + idx];
                as_[idx] = g_alpha[base2 + idx];
            }
        }
        __syncthreads();

        for (int tt = 0; tt < 32; tt++) {
            const float* kp = ks + tt * 64 + h * 16;
            float4 k0 = *(const float4*)(kp);
            float4 k1 = *(const float4*)(kp + 4);
            float4 k2 = *(const float4*)(kp + 8);
            float4 k3 = *(const float4*)(kp + 12);
            float kr[16] = {k0.x,k0.y,k0.z,k0.w, k1.x,k1.y,k1.z,k1.w,
                            k2.x,k2.y,k2.z,k2.w, k3.x,k3.y,k3.z,k3.w};

            float s0=0.f,s1=0.f,s2=0.f,s3=0.f;
#pragma unroll
            for (int u = 0; u < 4; u++) {
                s0 = fmaf(M[u],     kr[u],     s0);
                s1 = fmaf(M[4+u],   kr[4+u],   s1);
                s2 = fmaf(M[8+u],   kr[8+u],   s2);
                s3 = fmaf(M[12+u],  kr[12+u],  s3);
            }
            float Mk = (s0 + s1) + (s2 + s3);

            float a  = as_[tt * HEADS + h];
            float b  = bs [tt * HEADS + h];
            float vi = vs [tt * 64 + h * 16 + i];
            float cc = b * vi - a * Mk;

#pragma unroll
            for (int j = 0; j < 16; j++) M[j] = fmaf(kr[j], cc, M[j]);

            const float* qp = qs + tt * 64 + h * 16;
            float4 q0 = *(const float4*)(qp);
            float4 q1 = *(const float4*)(qp + 4);
            float4 q2 = *(const float4*)(qp + 8);
            float4 q3 = *(const float4*)(qp + 12);
            float qr[16] = {q0.x,q0.y,q0.z,q0.w, q1.x,q1.y,q1.z,q1.w,
                            q2.x,q2.y,q2.z,q2.w, q3.x,q3.y,q3.z,q3.w};

            float o0=0.f,o1=0.f,o2=0.f,o3=0.f;
#pragma unroll
            for (int u = 0; u < 4; u++) {
                o0 = fmaf(M[u],     qr[u],     o0);
                o1 = fmaf(M[4+u],   qr[4+u],   o1);
                o2 = fmaf(M[8+u],   qr[8+u],   o2);
                o3 = fmaf(M[12+u],  qr[12+u],  o3);
            }
            g_o[base + tt * 64 + h * 16 + i] = (o0 + o1) + (o2 + o3);
        }
        __syncthreads();
    }
}

// ---------------------------------------------------------------------------
// Kernel D (tf32 tensor): fib = o[131072,64] @ out_w^T[64,192] + out_b,
// scatter-store to (B,T,P,K). BM=128, BN=64, BK=32 (2 k-tiles).
// ---------------------------------------------------------------------------
__global__ __launch_bounds__(128) void gemmD_kernel(const float* __restrict__ ob,
                                                    float* __restrict__ out)
{
    __shared__ __align__(16) float As[128][ASTR];
    __shared__ __align__(16) float Bs[32][BSTR];

    const int tid  = threadIdx.x;
    const int lane = tid & 31;
    const int wid  = tid >> 5;
    const int g    = lane >> 2;
    const int t    = lane & 3;
    const int wm   = (wid >> 1) * 64;
    const int wn   = (wid & 1) * 32;
    const int m0   = blockIdx.y * 128;
    const int n0   = blockIdx.x * 64;

    float acc[4][4][4];
#pragma unroll
    for (int i = 0; i < 4; i++)
#pragma unroll
        for (int j = 0; j < 4; j++)
#pragma unroll
            for (int r = 0; r < 4; r++) acc[i][j][r] = 0.f;

    for (int k0 = 0; k0 < 64; k0 += 32) {
        // A tile from g_o: 128 x 32, cvt to tf32
#pragma unroll
        for (int i = 0; i < 8; i++) {
            int e   = i * 128 + tid;
            int row = e >> 3;
            int cq  = (e & 7) * 4;
            float4 av = *(const float4*)(g_o + (size_t)(m0 + row) * 64 + k0 + cq);
            float4 tv = make_float4(tf32r(av.x), tf32r(av.y), tf32r(av.z), tf32r(av.w));
            *(float4*)&As[row][cq] = tv;
        }
        // B tile from g_Bpack2 (already tf32)
#pragma unroll
        for (int i = 0; i < 4; i++) {
            int e  = i * 128 + tid;
            int kk = e >> 4;
            int cq = (e & 15) * 4;
            float4 bv = *(const float4*)(g_Bpack2 + (size_t)(k0 + kk) * KOUT + n0 + cq);
            *(float4*)&Bs[kk][cq] = bv;
        }
        __syncthreads();

#pragma unroll
        for (int ks = 0; ks < 4; ks++) {
            const int kb = ks * 8;
            unsigned a[4][4], b[4][2];
#pragma unroll
            for (int mt = 0; mt < 4; mt++) {
                int r = wm + mt * 16 + g;
                a[mt][0] = fu(As[r][kb + t]);
                a[mt][1] = fu(As[r + 8][kb + t]);
                a[mt][2] = fu(As[r][kb + t + 4]);
                a[mt][3] = fu(As[r + 8][kb + t + 4]);
            }
#pragma unroll
            for (int nt = 0; nt < 4; nt++) {
                int n = wn + nt * 8 + g;
                b[nt][0] = fu(Bs[kb + t][n]);
                b[nt][1] = fu(Bs[kb + t + 4][n]);
            }
#pragma unroll
            for (int mt = 0; mt < 4; mt++)
#pragma unroll
                for (int nt = 0; nt < 4; nt++)
                    MMA_TF32(acc[mt][nt], a[mt], b[nt]);
        }
        __syncthreads();
    }

    // scatter store: m = n*T + t; out[((b*T + t)*P + p)*K + col], + bias
    const int nseq = m0 >> 11;
    const int tb   = m0 & 2047;
    const int bb   = nseq >> 4;
    const int pp   = nseq & 15;
#pragma unroll
    for (int mt = 0; mt < 4; mt++) {
#pragma unroll
        for (int nt = 0; nt < 4; nt++) {
            int r   = wm + mt * 16 + g;
            int col = n0 + wn + nt * 8 + 2 * t;
            float b0 = ob[col], b1 = ob[col + 1];
            int t1 = tb + r;
            size_t d1 = (((size_t)bb * TLEN + t1) * 16 + pp) * KOUT + col;
            *(float2*)(out + d1) = make_float2(acc[mt][nt][0] + b0,
                                               acc[mt][nt][1] + b1);
            int t2 = t1 + 8;
            size_t d2 = (((size_t)bb * TLEN + t2) * 16 + pp) * KOUT + col;
            *(float2*)(out + d2) = make_float2(acc[mt][nt][2] + b0,
                                               acc[mt][nt][3] + b1);
        }
    }
}

// ---------------------------------------------------------------------------
// launch
// ---------------------------------------------------------------------------
extern "C" void kernel_launch(void* const* d_in, const int* in_sizes, int n_in,
                              void* d_out, int out_size)
{
    const float* joint = (const float*)d_in[0];
    const float* curv  = (const float*)d_in[1];
    const float* ent   = (const float*)d_in[2];
    const float* Wq    = (const float*)d_in[3];
    const float* Wk    = (const float*)d_in[4];
    const float* Wv    = (const float*)d_in[5];
    const float* Wbw   = (const float*)d_in[6];
    const float* Wbb   = (const float*)d_in[7];
    const float* Waw   = (const float*)d_in[8];
    const float* Wab   = (const float*)d_in[9];
    const float* cw    = (const float*)d_in[10];
    const float* ew    = (const float*)d_in[11];
    const float* out_w = (const float*)d_in[12];
    const float* out_b = (const float*)d_in[13];
    const float* lqw   = (const float*)d_in[14];
    const float* lqb   = (const float*)d_in[15];
    const float* lkw   = (const float*)d_in[16];
    const float* lkb   = (const float*)d_in[17];
    float* out = (float*)d_out;

    pack_kernel<<<256, 256>>>(Wq, Wk, Wv, out_w);

    gemmA_kernel<<<dim3(NPRE / 64, M_TOK / 128), 128>>>(joint);

    epilogue_kernel<<<M_TOK / 8, 256>>>(joint, curv, ent, Wbw, Wbb, Waw, Wab,
                                        cw, ew, lqw, lqb, lkw, lkb);

    scan_phase1<<<dim3(NSEQ, NCHUNK), 64>>>();
    scan_phase2<<<NSEQ, 64>>>();
    scan_phase3<<<dim3(NSEQ, NCHUNK), 64>>>();

    gemmD_kernel<<<dim3(KOUT / 64, M_TOK / 128), 128>>>(out_b, out);
}